// round 8
// baseline (speedup 1.0000x reference)
#include <cuda_runtime.h>
#include <math.h>

// Block floating-point quantization (block_size=16, mantissa_bits=8).
// Blocked-persistent kernel: 592 CTAs (148 SMs x 4), each owns a CONTIGUOUS
// range of 1024-float4 tiles and walks it linearly -> long sequential HBM
// streams (row-buffer friendly). Double-buffered: next tile's 4 loads are
// issued before the current tile's compute/stores, sustaining MLP across
// iterations (fixes R6's loop-serialization).
// 4 consecutive lanes share one 16-elem block; every LDG.128 fully coalesced.

#define TPB 256
#define CHUNKS 4
#define TILE (TPB * CHUNKS)   // 1024 float4 per tile (16KB)
#define NCTA 592              // 148 SMs * 4 CTAs/SM (fits ~52 regs at full residency)

__device__ __forceinline__ float absmax4(float4 v) {
    return fmaxf(fmaxf(fabsf(v.x), fabsf(v.y)), fmaxf(fabsf(v.z), fabsf(v.w)));
}

__device__ __forceinline__ int bfp_exp(float a) {
    int ef = (__float_as_int(a) >> 23) & 0xFF;
    return (ef != 0) ? (ef - 127) : ((a > 0.0f) ? ilogbf(a) : 0);
}

__device__ __forceinline__ float4 bfp_quant(float4 v, int e) {
    int eb = e - 7;
    float s  = __int_as_float((eb + 127) << 23);
    float is = __int_as_float((127 - eb) << 23);
    float4 r;
    r.x = fminf(fmaxf(rintf(v.x * is), -128.0f), 127.0f) * s;
    r.y = fminf(fmaxf(rintf(v.y * is), -128.0f), 127.0f) * s;
    r.z = fminf(fmaxf(rintf(v.z * is), -128.0f), 127.0f) * s;
    r.w = fminf(fmaxf(rintf(v.w * is), -128.0f), 127.0f) * s;
    return r;
}

__device__ __forceinline__ void process_store(
    const float4 v[CHUNKS], float4* __restrict__ out, size_t base)
{
    float a[CHUNKS];
    #pragma unroll
    for (int c = 0; c < CHUNKS; c++) a[c] = absmax4(v[c]);
    #pragma unroll
    for (int c = 0; c < CHUNKS; c++) a[c] = fmaxf(a[c], __shfl_xor_sync(0xffffffffu, a[c], 1));
    #pragma unroll
    for (int c = 0; c < CHUNKS; c++) a[c] = fmaxf(a[c], __shfl_xor_sync(0xffffffffu, a[c], 2));
    #pragma unroll
    for (int c = 0; c < CHUNKS; c++)
        __stcs(out + base + c * TPB, bfp_quant(v[c], bfp_exp(a[c])));
}

__global__ __launch_bounds__(TPB) void bfp_quant_kernel(
    const float4* __restrict__ in, float4* __restrict__ out, int n4)
{
    int ntiles = n4 / TILE;
    // contiguous block partition of tiles across CTAs
    int q = ntiles / gridDim.x;
    int r = ntiles - q * gridDim.x;
    int b = blockIdx.x;
    int t0  = b * q + (b < r ? b : r);
    int cnt = q + (b < r ? 1 : 0);

    size_t base = (size_t)t0 * TILE + threadIdx.x;

    if (cnt > 0) {
        float4 v[CHUNKS];
        #pragma unroll
        for (int c = 0; c < CHUNKS; c++) v[c] = __ldcs(in + base + c * TPB);

        for (int it = 1; it < cnt; it++) {
            size_t nbase = base + TILE;
            float4 w[CHUNKS];
            #pragma unroll
            for (int c = 0; c < CHUNKS; c++) w[c] = __ldcs(in + nbase + c * TPB);

            process_store(v, out, base);

            #pragma unroll
            for (int c = 0; c < CHUNKS; c++) v[c] = w[c];
            base = nbase;
        }
        process_store(v, out, base);
    }

    // remainder beyond full tiles (none for this shape): last CTA mops up
    int rem = ntiles * TILE;
    if (b == (int)gridDim.x - 1 && rem < n4) {
        for (int i = rem + threadIdx.x; i < n4; i += TPB) {
            float4 v = __ldcs(in + i);
            float a = absmax4(v);
            a = fmaxf(a, __shfl_xor_sync(0xffffffffu, a, 1));
            a = fmaxf(a, __shfl_xor_sync(0xffffffffu, a, 2));
            __stcs(out + i, bfp_quant(v, bfp_exp(a)));
        }
    }
}

extern "C" void kernel_launch(void* const* d_in, const int* in_sizes, int n_in,
                              void* d_out, int out_size)
{
    const float4* x = (const float4*)d_in[0];
    float4* out = (float4*)d_out;
    int n = in_sizes[0];           // 4*4096*4096 = 67108864
    int n4 = n / 4;                // 16777216 float4
    int ntiles = n4 / TILE;        // 16384
    int blocks = NCTA < ntiles ? NCTA : (ntiles > 0 ? ntiles : 1);
    bfp_quant_kernel<<<blocks, TPB>>>(x, out, n4);
}

// round 9
// speedup vs baseline: 1.1230x; 1.1230x over previous
#include <cuda_runtime.h>
#include <math.h>

// Block floating-point quantization (block_size=16, mantissa_bits=8).
// Final form: one-shot grid, 4 consecutive lanes share one 16-elem block
// (one float4 each) -> every LDG.128/STG.128 fully warp-coalesced (512B
// contiguous per warp). 4 front-batched streaming loads per thread (MLP_p1=4).
// __launch_bounds__(256,8) pins regs <=32 for 100% theoretical occupancy.
// Measured at the HBM read+write bus ceiling (~6.4 TB/s on GB300).

#define TPB 256
#define CHUNKS 4
#define TILE (TPB * CHUNKS)   // 1024 float4 per CTA

__device__ __forceinline__ float absmax4(float4 v) {
    return fmaxf(fmaxf(fabsf(v.x), fabsf(v.y)), fmaxf(fabsf(v.z), fabsf(v.w)));
}

__device__ __forceinline__ int bfp_exp(float a) {
    int ef = (__float_as_int(a) >> 23) & 0xFF;
    return (ef != 0) ? (ef - 127) : ((a > 0.0f) ? ilogbf(a) : 0);
}

__device__ __forceinline__ float4 bfp_quant(float4 v, int e) {
    int eb = e - 7;   // mantissa_bits - 1 = 7
    float s  = __int_as_float((eb + 127) << 23);
    float is = __int_as_float((127 - eb) << 23);
    float4 r;
    r.x = fminf(fmaxf(rintf(v.x * is), -128.0f), 127.0f) * s;
    r.y = fminf(fmaxf(rintf(v.y * is), -128.0f), 127.0f) * s;
    r.z = fminf(fmaxf(rintf(v.z * is), -128.0f), 127.0f) * s;
    r.w = fminf(fmaxf(rintf(v.w * is), -128.0f), 127.0f) * s;
    return r;
}

__global__ __launch_bounds__(TPB, 8) void bfp_quant_kernel(
    const float4* __restrict__ in, float4* __restrict__ out, int n4)
{
    int base = blockIdx.x * TILE + threadIdx.x;

    if (base + (CHUNKS - 1) * TPB < n4) {
        // ---- full-tile fast path: branch-free, 4 front-batched loads ----
        float4 v[CHUNKS];
        #pragma unroll
        for (int c = 0; c < CHUNKS; c++) v[c] = __ldcs(in + base + c * TPB);

        float a[CHUNKS];
        #pragma unroll
        for (int c = 0; c < CHUNKS; c++) a[c] = absmax4(v[c]);
        #pragma unroll
        for (int c = 0; c < CHUNKS; c++) a[c] = fmaxf(a[c], __shfl_xor_sync(0xffffffffu, a[c], 1));
        #pragma unroll
        for (int c = 0; c < CHUNKS; c++) a[c] = fmaxf(a[c], __shfl_xor_sync(0xffffffffu, a[c], 2));

        #pragma unroll
        for (int c = 0; c < CHUNKS; c++)
            __stcs(out + base + c * TPB, bfp_quant(v[c], bfp_exp(a[c])));
    } else {
        // ---- tail path (last CTA only; empty for this shape) ----
        #pragma unroll
        for (int c = 0; c < CHUNKS; c++) {
            int i = base + c * TPB;
            bool pred = i < n4;
            float4 v = pred ? __ldcs(in + i) : make_float4(0.f, 0.f, 0.f, 0.f);
            float a = absmax4(v);
            a = fmaxf(a, __shfl_xor_sync(0xffffffffu, a, 1));
            a = fmaxf(a, __shfl_xor_sync(0xffffffffu, a, 2));
            if (pred) __stcs(out + i, bfp_quant(v, bfp_exp(a)));
        }
    }
}

extern "C" void kernel_launch(void* const* d_in, const int* in_sizes, int n_in,
                              void* d_out, int out_size)
{
    const float4* x = (const float4*)d_in[0];
    float4* out = (float4*)d_out;
    int n = in_sizes[0];           // 4*4096*4096 = 67108864
    int n4 = n / 4;                // 16777216 float4
    int blocks = (n4 + TILE - 1) / TILE;   // 16384
    bfp_quant_kernel<<<blocks, TPB>>>(x, out, n4);
}

// round 10
// speedup vs baseline: 1.1261x; 1.0027x over previous
#include <cuda_runtime.h>
#include <math.h>

// Block floating-point quantization (block_size=16, mantissa_bits=8).
// FINAL: one-shot grid, 4 consecutive lanes share one 16-elem block (one
// float4 each) -> every LDG.128/STG.128 fully warp-coalesced (512B/warp).
// 6 front-batched streaming loads per thread (MLP_p1=6; ~288 loads in
// flight per SM at 60%+ occupancy). Measured at the GB300 HBM read+write
// bus ceiling (~6.4-6.5 TB/s, 80-82% of 8TB/s spec) across the full
// structural sweep (MLP 1-8, v4/v8, persistent/one-shot, blocked/interleaved).

#define TPB 256
#define CHUNKS 6
#define TILE (TPB * CHUNKS)   // 1536 float4 per CTA

__device__ __forceinline__ float absmax4(float4 v) {
    return fmaxf(fmaxf(fabsf(v.x), fabsf(v.y)), fmaxf(fabsf(v.z), fabsf(v.w)));
}

__device__ __forceinline__ int bfp_exp(float a) {
    // floor(log2(a)) for a>0; a==0 -> 0 (all-zero block quantizes to 0 anyway).
    // Denormal block max (exp field 0, a>0) via ilogbf — practically unreachable.
    int ef = (__float_as_int(a) >> 23) & 0xFF;
    return (ef != 0) ? (ef - 127) : ((a > 0.0f) ? ilogbf(a) : 0);
}

__device__ __forceinline__ float4 bfp_quant(float4 v, int e) {
    int eb = e - 7;   // mantissa_bits - 1 = 7
    float s  = __int_as_float((eb + 127) << 23);   // 2^(e-7)
    float is = __int_as_float((127 - eb) << 23);   // 2^(7-e)
    float4 r;
    r.x = fminf(fmaxf(rintf(v.x * is), -128.0f), 127.0f) * s;
    r.y = fminf(fmaxf(rintf(v.y * is), -128.0f), 127.0f) * s;
    r.z = fminf(fmaxf(rintf(v.z * is), -128.0f), 127.0f) * s;
    r.w = fminf(fmaxf(rintf(v.w * is), -128.0f), 127.0f) * s;
    return r;
}

__global__ __launch_bounds__(TPB, 6) void bfp_quant_kernel(
    const float4* __restrict__ in, float4* __restrict__ out, int n4)
{
    int base = blockIdx.x * TILE + threadIdx.x;

    if (base + (CHUNKS - 1) * TPB < n4) {
        // ---- full-tile fast path: branch-free, 6 front-batched loads ----
        float4 v[CHUNKS];
        #pragma unroll
        for (int c = 0; c < CHUNKS; c++) v[c] = __ldcs(in + base + c * TPB);

        float a[CHUNKS];
        #pragma unroll
        for (int c = 0; c < CHUNKS; c++) a[c] = absmax4(v[c]);
        #pragma unroll
        for (int c = 0; c < CHUNKS; c++) a[c] = fmaxf(a[c], __shfl_xor_sync(0xffffffffu, a[c], 1));
        #pragma unroll
        for (int c = 0; c < CHUNKS; c++) a[c] = fmaxf(a[c], __shfl_xor_sync(0xffffffffu, a[c], 2));

        #pragma unroll
        for (int c = 0; c < CHUNKS; c++)
            __stcs(out + base + c * TPB, bfp_quant(v[c], bfp_exp(a[c])));
    } else {
        // ---- tail path (last CTA only) ----
        #pragma unroll
        for (int c = 0; c < CHUNKS; c++) {
            int i = base + c * TPB;
            bool pred = i < n4;
            float4 v = pred ? __ldcs(in + i) : make_float4(0.f, 0.f, 0.f, 0.f);
            float a = absmax4(v);
            a = fmaxf(a, __shfl_xor_sync(0xffffffffu, a, 1));
            a = fmaxf(a, __shfl_xor_sync(0xffffffffu, a, 2));
            if (pred) __stcs(out + i, bfp_quant(v, bfp_exp(a)));
        }
    }
}

extern "C" void kernel_launch(void* const* d_in, const int* in_sizes, int n_in,
                              void* d_out, int out_size)
{
    const float4* x = (const float4*)d_in[0];
    float4* out = (float4*)d_out;
    int n = in_sizes[0];           // 4*4096*4096 = 67108864
    int n4 = n / 4;                // 16777216 float4
    int blocks = (n4 + TILE - 1) / TILE;   // 10923
    bfp_quant_kernel<<<blocks, TPB>>>(x, out, n4);
}